// round 7
// baseline (speedup 1.0000x reference)
#include <cuda_runtime.h>
#include <cuda_bf16.h>

#define OUT_W    256
#define IMG_W    512
#define NPAIR    128            // one block per ii-pair
#define SK_T     33             // K rows per block
#define SK_E     792            // bf16/row; stride 1584B = 48 mod 128 -> conflict-free
#define SK_W     396            // u32 words per row
#define SREV_LEN 1032
#define OFF_K     0
#define OFF_SREV  52272         // 33*396*4
#define OFF_SREVB 56400         // + 2*1032*2
#define SMEM_BYTES 60544

__device__ float g_part[NPAIR * 32 * OUT_W];    // 4 MB partials [p][i][j]
__device__ float g_red[8 * 32 * OUT_W];         // 256 KB stage-A output

__device__ __forceinline__ float frcp(float x) {
    float r; asm("rcp.approx.f32 %0, %1;" : "=f"(r) : "f"(x)); return r;
}
__device__ __forceinline__ void mma_bf16(float* d, unsigned a0, unsigned a1,
                                         unsigned a2, unsigned a3,
                                         unsigned b0, unsigned b1) {
    asm volatile(
        "mma.sync.aligned.m16n8k16.row.col.f32.bf16.bf16.f32 "
        "{%0,%1,%2,%3}, {%4,%5,%6,%7}, {%8,%9}, {%0,%1,%2,%3};"
        : "+f"(d[0]), "+f"(d[1]), "+f"(d[2]), "+f"(d[3])
        : "r"(a0), "r"(a1), "r"(a2), "r"(a3), "r"(b0), "r"(b1));
}

// ---------------------------------------------------------------------------
// Block p: ii in {2p, 2p+1}, full i in [0,32). 512 threads; warp w owns
// j in [16w, 16w+16) (1 m-tile) x 4 n-tiles, k = e in [16w, 16w+544).
// A = Toeplitz of reversed image row, read in place (a3 == a0); B = 33
// staged K rows built in-SMEM. Inner loop double-buffered.
// ---------------------------------------------------------------------------
__global__ void __launch_bounds__(512, 1)
conv_mma_kernel(const float* __restrict__ img, const float* __restrict__ pos) {
    extern __shared__ char smem[];
    unsigned*      skw = (unsigned*)(smem + OFF_K);
    __nv_bfloat16* sr  = (__nv_bfloat16*)(smem + OFF_SREV);   // [2][1032]
    __nv_bfloat16* srB = (__nv_bfloat16*)(smem + OFF_SREVB);  // shifted +1

    const int p   = blockIdx.x;
    const int tid = threadIdx.x;
    const float p0 = pos[0], p1 = pos[1];

    // ---- reversed image rows (bf16): sr[s][z] = img[2p+s][767-z], z in [256,767]
    for (int x = tid; x < 2 * SREV_LEN; x += 512) {
        int s = (x >= SREV_LEN) ? 1 : 0;
        int z = x - s * SREV_LEN;
        float v0 = (z >= 256 && z <= 767) ? img[(2 * p + s) * IMG_W + (767 - z)] : 0.f;
        int z1 = z + 1;
        float v1 = (z1 >= 256 && z1 <= 767) ? img[(2 * p + s) * IMG_W + (767 - z1)] : 0.f;
        sr [x] = __float2bfloat16_rn(v0);
        srB[x] = __float2bfloat16_rn(v1);
    }
    // ---- K rows: row t holds d-255 = t - 1 - 2p ; e = 2u, 2u+1 (zero for e>766)
    for (int t = 0; t < SK_T; t++) {
        float dx  = (float)(t - 1 - 2 * p) + p0;
        float dx2 = dx * dx;
        for (int u = tid; u < SK_W; u += 512) {
            float dy0 = (float)(2 * u - 511) + p1;
            float dy1 = dy0 + 1.0f;
            float v0 = (2 * u     < 767) ? frcp(fmaf(dy0, dy0, dx2)) : 0.f;
            float v1 = (2 * u + 1 < 767) ? frcp(fmaf(dy1, dy1, dx2)) : 0.f;
            unsigned wv;
            asm("cvt.rn.bf16x2.f32 %0, %1, %2;" : "=r"(wv) : "f"(v1), "f"(v0));
            skw[t * SK_W + u] = wv;
        }
    }
    __syncthreads();

    const int w    = tid >> 5;        // 16 warps: j strip [16w, 16w+16)
    const int lane = tid & 31;
    const int r    = lane >> 2;
    const int c    = lane & 3;
    const int jbase = 16 * w;
    const int sel   = r & 1;
    const int aw0   = (2 * c - jbase - r + 256 - sel) >> 1;

    float acc[4][4];
#pragma unroll
    for (int n = 0; n < 4; n++)
#pragma unroll
        for (int k = 0; k < 4; k++) acc[n][k] = 0.f;

#define LOADQ(A_, B_, As_, pB_, wA_)                                          \
    {                                                                         \
        A_[0] = As_[wA_]; A_[1] = As_[wA_ - 4]; A_[2] = As_[wA_ + 4];         \
        B_[0] = pB_[0];              B_[1] = pB_[4];                          \
        B_[2] = pB_[8 * SK_W];       B_[3] = pB_[8 * SK_W + 4];               \
        B_[4] = pB_[16 * SK_W];      B_[5] = pB_[16 * SK_W + 4];              \
        B_[6] = pB_[24 * SK_W];      B_[7] = pB_[24 * SK_W + 4];              \
    }
#define MMAQ(A_, B_)                                                          \
    {                                                                         \
        mma_bf16(acc[0], A_[0], A_[1], A_[2], A_[0], B_[0], B_[1]);           \
        mma_bf16(acc[1], A_[0], A_[1], A_[2], A_[0], B_[2], B_[3]);           \
        mma_bf16(acc[2], A_[0], A_[1], A_[2], A_[0], B_[4], B_[5]);           \
        mma_bf16(acc[3], A_[0], A_[1], A_[2], A_[0], B_[6], B_[7]);           \
    }

#pragma unroll 1
    for (int s = 0; s < 2; s++) {
        const unsigned* As = (const unsigned*)(sel ? (srB + s * SREV_LEN)
                                                   : (sr  + s * SREV_LEN));
        const unsigned* pB = skw + (r + 1 - s) * SK_W + c + 8 * w;
        int wA = aw0 + 8 * w;

        unsigned aX[3], bX[8], aY[3], bY[8];
        LOADQ(aX, bX, As, pB, wA); wA += 8; pB += 8;
#pragma unroll 1
        for (int it = 0; it < 16; it++) {
            LOADQ(aY, bY, As, pB, wA); wA += 8; pB += 8;
            MMAQ(aX, bX);
            LOADQ(aX, bX, As, pB, wA); wA += 8; pB += 8;
            MMAQ(aY, bY);
        }
        LOADQ(aY, bY, As, pB, wA);
        MMAQ(aX, bX);
        MMAQ(aY, bY);
    }
#undef LOADQ
#undef MMAQ

    // ---- partials [p][i][j]: D row = j (j0, j0+8), col = i (2c, 2c+1)
    float* dst = g_part + p * (32 * OUT_W);
    const int j0 = jbase + r;
#pragma unroll
    for (int n = 0; n < 4; n++) {
        const int i0 = 8 * n + 2 * c;
        dst[(i0    ) * OUT_W + j0    ] = acc[n][0];
        dst[(i0 + 1) * OUT_W + j0    ] = acc[n][1];
        dst[(i0    ) * OUT_W + j0 + 8] = acc[n][2];
        dst[(i0 + 1) * OUT_W + j0 + 8] = acc[n][3];
    }
}

// ---------------------------------------------------------------------------
// Two-stage deterministic reduction over the 128 ii-pair chunks.
// ---------------------------------------------------------------------------
__global__ void reduce_a_kernel() {
    const int g  = blockIdx.x >> 5;
    const int o  = (blockIdx.x & 31) * 256 + threadIdx.x;
    const int c0 = g * 16;
    float s0 = 0.f, s1 = 0.f, s2 = 0.f, s3 = 0.f;
#pragma unroll
    for (int c = 0; c < 16; c += 4) {
        s0 += g_part[(c0 + c + 0) * 8192 + o];
        s1 += g_part[(c0 + c + 1) * 8192 + o];
        s2 += g_part[(c0 + c + 2) * 8192 + o];
        s3 += g_part[(c0 + c + 3) * 8192 + o];
    }
    g_red[g * 8192 + o] = (s0 + s1) + (s2 + s3);
}

__global__ void reduce_b_kernel(float* __restrict__ out) {
    const int o = blockIdx.x * 256 + threadIdx.x;
    float s = 0.f;
#pragma unroll
    for (int g = 0; g < 8; g++) s += g_red[g * 8192 + o];
    out[o] = s;
}

// ---------------------------------------------------------------------------
extern "C" void kernel_launch(void* const* d_in, const int* in_sizes, int n_in,
                              void* d_out, int out_size) {
    const float* img = (const float*)d_in[0];   // [256, 512] f32
    const float* pos = (const float*)d_in[1];   // [2] f32
    float* out = (float*)d_out;                 // [32, 256] f32

    cudaFuncSetAttribute(conv_mma_kernel,
                         cudaFuncAttributeMaxDynamicSharedMemorySize, SMEM_BYTES);
    conv_mma_kernel<<<NPAIR, 512, SMEM_BYTES>>>(img, pos);
    reduce_a_kernel<<<256, 256>>>();
    reduce_b_kernel<<<32, 256>>>(out);
}